// round 3
// baseline (speedup 1.0000x reference)
#include <cuda_runtime.h>
#include <cuda_fp16.h>
#include <cstdint>

#define T_STEPS 8192
#define O_DIM   1024
#define H_DIM   2048
#define A_DIM   512
#define G3H     (3*H_DIM)

// Scan persistent-kernel config: 147 blocks x 14 hidden units, 1 warp per unit.
#define SCAN_NB      147
#define SCAN_UPB     14
#define SCAN_THREADS (SCAN_UPB*32)
#define SCAN_SMEM    (SCAN_UPB*3*H_DIM*2)   // fp16 weights: 172032 bytes

// ---------------- scratch (device globals: allocation-free rule) ------------
__device__ float  g_xi[(size_t)T_STEPS * G3H];    // 192 MB: precomputed input projections
__device__ float  g_hs[(size_t)T_STEPS * H_DIM];  // 64 MB: hidden states h[1..T]
__device__ __half g_whh[(size_t)G3H * H_DIM];     // 24 MB: fp16 W_hh, unit-major layout
__device__ unsigned g_bar_cnt;                     // grid barrier counter (self-resetting)
__device__ volatile unsigned g_bar_gen;            // grid barrier generation (monotonic)

// ---------------- W_hh fp32 -> fp16 with unit-major relayout ----------------
// dst layout: for hidden unit j, its 3 gate rows (r,z,n) are contiguous:
//   g_whh[(j*3+g)*H_DIM + k] = W_hh[g*H_DIM + j][k]
__global__ void convert_whh_kernel(const float* __restrict__ W) {
    size_t idx = (size_t)blockIdx.x * blockDim.x + threadIdx.x;
    if (idx >= (size_t)G3H * H_DIM) return;
    int row = (int)(idx / H_DIM);
    int k   = (int)(idx % H_DIM);
    int g = row >> 11;            // row / 2048
    int j = row & (H_DIM - 1);    // row % 2048
    g_whh[((size_t)j*3 + g)*H_DIM + k] = __float2half_rn(W[idx]);
}

// ---------------- generic C = A * B^T + bias (fp32 SIMT, 128x128x16) --------
// A: [M,K] row-major, B: [N,K] row-major, C: [M,N] row-major. M,N % 128 == 0, K % 16 == 0.
__global__ __launch_bounds__(256) void gemm_abt_kernel(
    const float* __restrict__ A, const float* __restrict__ B,
    const float* __restrict__ bias, float* __restrict__ C,
    int M, int N, int K)
{
    __shared__ __align__(16) float As[16][132];
    __shared__ __align__(16) float Bs[16][132];
    const int tid = threadIdx.x;
    const int tx = tid & 15, ty = tid >> 4;
    const int m0 = blockIdx.y * 128, n0 = blockIdx.x * 128;

    float acc[8][8];
    #pragma unroll
    for (int i = 0; i < 8; i++)
        #pragma unroll
        for (int j = 0; j < 8; j++) acc[i][j] = 0.0f;

    for (int kt = 0; kt < K; kt += 16) {
        #pragma unroll
        for (int s = 0; s < 2; s++) {
            int f = tid + s*256;          // 512 float4 loads per operand tile
            int row = f >> 2;
            int kq = (f & 3) << 2;
            float4 va = *(const float4*)(A + (size_t)(m0+row)*K + kt + kq);
            As[kq+0][row] = va.x; As[kq+1][row] = va.y;
            As[kq+2][row] = va.z; As[kq+3][row] = va.w;
            float4 vb = *(const float4*)(B + (size_t)(n0+row)*K + kt + kq);
            Bs[kq+0][row] = vb.x; Bs[kq+1][row] = vb.y;
            Bs[kq+2][row] = vb.z; Bs[kq+3][row] = vb.w;
        }
        __syncthreads();
        #pragma unroll
        for (int k = 0; k < 16; k++) {
            float a[8], bb[8];
            *(float4*)(a)    = *(const float4*)&As[k][ty*8];
            *(float4*)(a+4)  = *(const float4*)&As[k][ty*8+4];
            *(float4*)(bb)   = *(const float4*)&Bs[k][tx*8];
            *(float4*)(bb+4) = *(const float4*)&Bs[k][tx*8+4];
            #pragma unroll
            for (int i = 0; i < 8; i++)
                #pragma unroll
                for (int j = 0; j < 8; j++)
                    acc[i][j] = fmaf(a[i], bb[j], acc[i][j]);
        }
        __syncthreads();
    }

    float4 bv0 = *(const float4*)&bias[n0 + tx*8];
    float4 bv1 = *(const float4*)&bias[n0 + tx*8 + 4];
    #pragma unroll
    for (int i = 0; i < 8; i++) {
        float4 o0, o1;
        o0.x = acc[i][0]+bv0.x; o0.y = acc[i][1]+bv0.y;
        o0.z = acc[i][2]+bv0.z; o0.w = acc[i][3]+bv0.w;
        o1.x = acc[i][4]+bv1.x; o1.y = acc[i][5]+bv1.y;
        o1.z = acc[i][6]+bv1.z; o1.w = acc[i][7]+bv1.w;
        float* crow = C + (size_t)(m0 + ty*8 + i)*N + n0 + tx*8;
        *(float4*)(crow)   = o0;
        *(float4*)(crow+4) = o1;
    }
}

// ---------------- GRU scan (persistent, one grid barrier per step) ----------
__device__ __forceinline__ float sigmoid_f(float x) {
    return 1.0f / (1.0f + __expf(-x));
}
__device__ __forceinline__ float tanh_f(float x) {
    // accurate tanh from __expf (avoid tanh.approx's 6e-4 abs error)
    float e = __expf(-2.0f * fabsf(x));
    float t = (1.0f - e) / (1.0f + e);
    return copysignf(t, x);
}
__device__ __forceinline__ float dot8(float acc, uint4 q, float4 ha, float4 hb) {
    float2 p;
    p = __half22float2(*reinterpret_cast<const __half2*>(&q.x));
    acc = fmaf(p.x, ha.x, acc); acc = fmaf(p.y, ha.y, acc);
    p = __half22float2(*reinterpret_cast<const __half2*>(&q.y));
    acc = fmaf(p.x, ha.z, acc); acc = fmaf(p.y, ha.w, acc);
    p = __half22float2(*reinterpret_cast<const __half2*>(&q.z));
    acc = fmaf(p.x, hb.x, acc); acc = fmaf(p.y, hb.y, acc);
    p = __half22float2(*reinterpret_cast<const __half2*>(&q.w));
    acc = fmaf(p.x, hb.z, acc); acc = fmaf(p.y, hb.w, acc);
    return acc;
}

__global__ __launch_bounds__(SCAN_THREADS) void gru_scan_kernel(const float* __restrict__ b_hh)
{
    extern __shared__ __align__(16) char smem_raw[];
    __half* sw = reinterpret_cast<__half*>(smem_raw);

    const int b    = blockIdx.x;
    const int tid  = threadIdx.x;
    const int u    = tid >> 5;      // warp id = unit within block
    const int lane = tid & 31;
    const int j    = b * SCAN_UPB + u;     // global hidden unit
    const bool active = (j < H_DIM);

    // Load this unit's 3 gate rows (12 KB) into SMEM once; resident for all 8192 steps.
    if (active) {
        const uint4* src = reinterpret_cast<const uint4*>(g_whh + (size_t)j*3*H_DIM);
        uint4* dst = reinterpret_cast<uint4*>(sw + (size_t)u*3*H_DIM);
        #pragma unroll
        for (int i = 0; i < 24; i++) dst[i*32 + lane] = src[i*32 + lane];
    }
    float bhr = 0.f, bhz = 0.f, bhn = 0.f;
    if (active) { bhr = b_hh[j]; bhz = b_hh[H_DIM+j]; bhn = b_hh[2*H_DIM+j]; }
    __syncthreads();

    const __half* w0 = sw + (size_t)u*3*H_DIM;   // r row
    const __half* w1 = w0 + H_DIM;               // z row
    const __half* w2 = w1 + H_DIM;               // n row

    for (int t = 0; t < T_STEPS; t++) {
        // Prefetch per-unit scalars early (xi lives in DRAM; hide latency under GEMV).
        float xr = 0.f, xz = 0.f, xn = 0.f, hprev = 0.f;
        if (active && lane == 0) {
            const float* xirow = g_xi + (size_t)t*G3H;
            xr = xirow[j]; xz = xirow[H_DIM+j]; xn = xirow[2*H_DIM+j];
            hprev = (t > 0) ? g_hs[(size_t)(t-1)*H_DIM + j] : 0.0f;
        }

        float a0 = 0.f, a1 = 0.f, a2 = 0.f;
        if (active && t > 0) {
            const float* hp = g_hs + (size_t)(t-1)*H_DIM;
            float4 h[16];                         // this lane's 64 h values (MLP=16 batch)
            #pragma unroll
            for (int c = 0; c < 8; c++) {
                const float* p = hp + c*256 + lane*8;
                h[2*c]   = *(const float4*)(p);
                h[2*c+1] = *(const float4*)(p + 4);
            }
            #pragma unroll
            for (int c = 0; c < 8; c++) {
                const int kb = c*256 + lane*8;    // conflict-free LDS.128 across warp
                uint4 q0 = *(const uint4*)(w0 + kb);
                uint4 q1 = *(const uint4*)(w1 + kb);
                uint4 q2 = *(const uint4*)(w2 + kb);
                a0 = dot8(a0, q0, h[2*c], h[2*c+1]);
                a1 = dot8(a1, q1, h[2*c], h[2*c+1]);
                a2 = dot8(a2, q2, h[2*c], h[2*c+1]);
            }
        }
        #pragma unroll
        for (int off = 16; off > 0; off >>= 1) {
            a0 += __shfl_xor_sync(0xffffffffu, a0, off);
            a1 += __shfl_xor_sync(0xffffffffu, a1, off);
            a2 += __shfl_xor_sync(0xffffffffu, a2, off);
        }
        if (active && lane == 0) {
            float r = sigmoid_f(xr + a0 + bhr);
            float z = sigmoid_f(xz + a1 + bhz);
            float n = tanh_f(xn + r*(a2 + bhn));
            g_hs[(size_t)t*H_DIM + j] = (1.0f - z)*n + z*hprev;
        }

        // ---- grid barrier (sense-reversing; all 147 CTAs co-resident) ----
        __threadfence();
        __syncthreads();
        if (tid == 0) {
            unsigned gen = g_bar_gen;                       // read BEFORE arrive
            if (atomicAdd(&g_bar_cnt, 1u) == SCAN_NB - 1u) {
                g_bar_cnt = 0u;                              // reset before release
                __threadfence();
                g_bar_gen = gen + 1u;                        // release
            } else {
                while (g_bar_gen == gen) { }                 // spin on L2 (volatile)
            }
            __threadfence();
        }
        __syncthreads();
    }
}

// ---------------- launch ----------------------------------------------------
extern "C" void kernel_launch(void* const* d_in, const int* in_sizes, int n_in,
                              void* d_out, int out_size)
{
    const float* obs  = (const float*)d_in[0];
    const float* W_ih = (const float*)d_in[1];
    const float* W_hh = (const float*)d_in[2];
    const float* b_ih = (const float*)d_in[3];
    const float* b_hh = (const float*)d_in[4];
    const float* W_o  = (const float*)d_in[5];
    const float* b_o  = (const float*)d_in[6];
    const float* W_d  = (const float*)d_in[7];
    const float* b_d  = (const float*)d_in[8];
    float* out = (float*)d_out;

    float* xi = nullptr; float* hs = nullptr;
    cudaGetSymbolAddress((void**)&xi, g_xi);
    cudaGetSymbolAddress((void**)&hs, g_hs);

    // 1) W_hh -> fp16 unit-major
    {
        size_t total = (size_t)G3H * H_DIM;
        int blocks = (int)((total + 255) / 256);
        convert_whh_kernel<<<blocks, 256>>>(W_hh);
    }

    // 2) xi = obs @ W_ih^T + b_ih   [8192 x 6144], K=1024
    gemm_abt_kernel<<<dim3(G3H/128, T_STEPS/128), 256>>>(
        obs, W_ih, b_ih, xi, T_STEPS, G3H, O_DIM);

    // 3) sequential GRU scan (persistent kernel, 8192 internal steps)
    cudaFuncSetAttribute(gru_scan_kernel,
                         cudaFuncAttributeMaxDynamicSharedMemorySize, SCAN_SMEM);
    gru_scan_kernel<<<SCAN_NB, SCAN_THREADS, SCAN_SMEM>>>(b_hh);

    // 4) o_logits = hs @ W_o^T + b_o ; d_logits = hs @ W_d^T + b_d
    gemm_abt_kernel<<<dim3(A_DIM/128, T_STEPS/128), 256>>>(
        hs, W_o, b_o, out, T_STEPS, A_DIM, H_DIM);
    gemm_abt_kernel<<<dim3(A_DIM/128, T_STEPS/128), 256>>>(
        hs, W_d, b_d, out + (size_t)T_STEPS * A_DIM, T_STEPS, A_DIM, H_DIM);
}

// round 4
// speedup vs baseline: 1.0342x; 1.0342x over previous
#include <cuda_runtime.h>
#include <cuda_fp16.h>
#include <cstdint>

#define T_STEPS 8192
#define O_DIM   1024
#define H_DIM   2048
#define A_DIM   512
#define G3H     (3*H_DIM)

// Scan persistent-kernel config: 147 blocks x 14 hidden units, 1 warp per unit.
#define SCAN_NB      147
#define SCAN_UPB     14
#define SCAN_THREADS (SCAN_UPB*32)
// SMEM: fp16 weights (14*3*2048*2 = 172032 B) + h staging (2048 f32 = 8192 B)
#define SCAN_W_BYTES (SCAN_UPB*3*H_DIM*2)
#define SCAN_SMEM    (SCAN_W_BYTES + H_DIM*4)

// ---------------- scratch (device globals: allocation-free rule) ------------
__device__ float  g_xi[(size_t)T_STEPS * G3H];    // 192 MB: precomputed input projections
__device__ float  g_hs[(size_t)T_STEPS * H_DIM];  // 64 MB: hidden states h[1..T]
__device__ __half g_whh[(size_t)G3H * H_DIM];     // 24 MB: fp16 W_hh, permuted layout
__device__ unsigned g_bar_cnt;                     // grid barrier counter (self-resetting)
__device__ unsigned g_bar_gen;                     // grid barrier generation (monotonic)

// ---------------- W_hh fp32 -> fp16 permuted relayout ------------------------
// Permuted layout (uint4 granularity): for unit j, gate g, chunk c (0..7), lane l (0..31),
// the uint4 at index ((j*3+g)*8 + c)*32 + l holds 8 fp16 weights for source columns
//   k = c*256 + l*4 + {0..3}  and  k = c*256 + 128 + l*4 + {0..3}
// so that in the scan, lane l's h operands are two CONTIGUOUS float4 LDS.128 loads
// (conflict-free) and its weights are one contiguous LDS.128.
__global__ void convert_whh_kernel(const float* __restrict__ W) {
    int idx = blockIdx.x * blockDim.x + threadIdx.x;      // 0 .. 6144*256-1
    if (idx >= H_DIM * 3 * 8 * 32) return;
    int l  = idx & 31;
    int c  = (idx >> 5) & 7;
    int gj = idx >> 8;            // j*3 + g
    int g  = gj % 3;
    int j  = gj / 3;
    const float* src = W + (size_t)(g*H_DIM + j)*H_DIM + c*256 + l*4;
    float4 v0 = *(const float4*)src;
    float4 v1 = *(const float4*)(src + 128);
    __half2 q0 = __floats2half2_rn(v0.x, v0.y);
    __half2 q1 = __floats2half2_rn(v0.z, v0.w);
    __half2 q2 = __floats2half2_rn(v1.x, v1.y);
    __half2 q3 = __floats2half2_rn(v1.z, v1.w);
    uint4 o;
    o.x = *reinterpret_cast<unsigned*>(&q0);
    o.y = *reinterpret_cast<unsigned*>(&q1);
    o.z = *reinterpret_cast<unsigned*>(&q2);
    o.w = *reinterpret_cast<unsigned*>(&q3);
    reinterpret_cast<uint4*>(g_whh)[(size_t)idx] = o;     // dst index == idx by construction
}

// ---------------- generic C = A * B^T + bias (fp32 SIMT, 128x128x16) --------
__global__ __launch_bounds__(256) void gemm_abt_kernel(
    const float* __restrict__ A, const float* __restrict__ B,
    const float* __restrict__ bias, float* __restrict__ C,
    int M, int N, int K)
{
    __shared__ __align__(16) float As[16][132];
    __shared__ __align__(16) float Bs[16][132];
    const int tid = threadIdx.x;
    const int tx = tid & 15, ty = tid >> 4;
    const int m0 = blockIdx.y * 128, n0 = blockIdx.x * 128;

    float acc[8][8];
    #pragma unroll
    for (int i = 0; i < 8; i++)
        #pragma unroll
        for (int j = 0; j < 8; j++) acc[i][j] = 0.0f;

    for (int kt = 0; kt < K; kt += 16) {
        #pragma unroll
        for (int s = 0; s < 2; s++) {
            int f = tid + s*256;
            int row = f >> 2;
            int kq = (f & 3) << 2;
            float4 va = *(const float4*)(A + (size_t)(m0+row)*K + kt + kq);
            As[kq+0][row] = va.x; As[kq+1][row] = va.y;
            As[kq+2][row] = va.z; As[kq+3][row] = va.w;
            float4 vb = *(const float4*)(B + (size_t)(n0+row)*K + kt + kq);
            Bs[kq+0][row] = vb.x; Bs[kq+1][row] = vb.y;
            Bs[kq+2][row] = vb.z; Bs[kq+3][row] = vb.w;
        }
        __syncthreads();
        #pragma unroll
        for (int k = 0; k < 16; k++) {
            float a[8], bb[8];
            *(float4*)(a)    = *(const float4*)&As[k][ty*8];
            *(float4*)(a+4)  = *(const float4*)&As[k][ty*8+4];
            *(float4*)(bb)   = *(const float4*)&Bs[k][tx*8];
            *(float4*)(bb+4) = *(const float4*)&Bs[k][tx*8+4];
            #pragma unroll
            for (int i = 0; i < 8; i++)
                #pragma unroll
                for (int j = 0; j < 8; j++)
                    acc[i][j] = fmaf(a[i], bb[j], acc[i][j]);
        }
        __syncthreads();
    }

    float4 bv0 = *(const float4*)&bias[n0 + tx*8];
    float4 bv1 = *(const float4*)&bias[n0 + tx*8 + 4];
    #pragma unroll
    for (int i = 0; i < 8; i++) {
        float4 o0, o1;
        o0.x = acc[i][0]+bv0.x; o0.y = acc[i][1]+bv0.y;
        o0.z = acc[i][2]+bv0.z; o0.w = acc[i][3]+bv0.w;
        o1.x = acc[i][4]+bv1.x; o1.y = acc[i][5]+bv1.y;
        o1.z = acc[i][6]+bv1.z; o1.w = acc[i][7]+bv1.w;
        float* crow = C + (size_t)(m0 + ty*8 + i)*N + n0 + tx*8;
        *(float4*)(crow)   = o0;
        *(float4*)(crow+4) = o1;
    }
}

// ---------------- scan helpers ----------------------------------------------
__device__ __forceinline__ float sigmoid_f(float x) {
    return 1.0f / (1.0f + __expf(-x));
}
__device__ __forceinline__ float tanh_f(float x) {
    float e = __expf(-2.0f * fabsf(x));
    float t = (1.0f - e) / (1.0f + e);
    return copysignf(t, x);
}
__device__ __forceinline__ unsigned long long pk2(float x, float y) {
    unsigned long long r;
    asm("mov.b64 %0, {%1, %2};" : "=l"(r) : "f"(x), "f"(y));
    return r;
}
// 8 fp16 weights (uint4) x 8 fp32 h values (4 packed f32x2) -> packed f32x2 acc
__device__ __forceinline__ void fma8(unsigned long long& acc, uint4 wq,
    unsigned long long h01, unsigned long long h23,
    unsigned long long h45, unsigned long long h67)
{
    asm("{\n\t"
        ".reg .b16 a, b;\n\t"
        ".reg .f32 lo, hi;\n\t"
        ".reg .b64 w;\n\t"
        "mov.b32 {a, b}, %1;\n\t"
        "cvt.f32.f16 lo, a; cvt.f32.f16 hi, b;\n\t"
        "mov.b64 w, {lo, hi};\n\t"
        "fma.rn.f32x2 %0, w, %5, %0;\n\t"
        "mov.b32 {a, b}, %2;\n\t"
        "cvt.f32.f16 lo, a; cvt.f32.f16 hi, b;\n\t"
        "mov.b64 w, {lo, hi};\n\t"
        "fma.rn.f32x2 %0, w, %6, %0;\n\t"
        "mov.b32 {a, b}, %3;\n\t"
        "cvt.f32.f16 lo, a; cvt.f32.f16 hi, b;\n\t"
        "mov.b64 w, {lo, hi};\n\t"
        "fma.rn.f32x2 %0, w, %7, %0;\n\t"
        "mov.b32 {a, b}, %4;\n\t"
        "cvt.f32.f16 lo, a; cvt.f32.f16 hi, b;\n\t"
        "mov.b64 w, {lo, hi};\n\t"
        "fma.rn.f32x2 %0, w, %8, %0;\n\t"
        "}"
        : "+l"(acc)
        : "r"(wq.x), "r"(wq.y), "r"(wq.z), "r"(wq.w),
          "l"(h01), "l"(h23), "l"(h45), "l"(h67));
}
__device__ __forceinline__ float unpack_sum(unsigned long long a) {
    float lo, hi;
    asm("mov.b64 {%0, %1}, %2;" : "=f"(lo), "=f"(hi) : "l"(a));
    return lo + hi;
}

// ---------------- GRU scan (persistent, h staged via SMEM) -------------------
__global__ __launch_bounds__(SCAN_THREADS) void gru_scan_kernel(const float* __restrict__ b_hh)
{
    extern __shared__ __align__(16) char smem_raw[];
    uint4* sw4    = reinterpret_cast<uint4*>(smem_raw);                 // weights, uint4 view
    float* smem_h = reinterpret_cast<float*>(smem_raw + SCAN_W_BYTES);  // h vector [2048]

    const int b    = blockIdx.x;
    const int tid  = threadIdx.x;
    const int u    = tid >> 5;
    const int lane = tid & 31;
    const int j    = b * SCAN_UPB + u;
    const bool active = (j < H_DIM);

    // Zero all SMEM (weights region for inactive tail warps + h for t=0).
    for (int i = tid; i < SCAN_SMEM/16; i += SCAN_THREADS)
        sw4[i] = make_uint4(0,0,0,0);
    __syncthreads();

    // Load this unit's permuted weights (768 uint4 = 12 KB) into SMEM once.
    if (active) {
        const uint4* src = reinterpret_cast<const uint4*>(g_whh) + (size_t)j*768;
        uint4* dst = sw4 + (size_t)u*768;
        #pragma unroll
        for (int i = 0; i < 24; i++) dst[i*32 + lane] = src[i*32 + lane];
    }
    float bhr = 0.f, bhz = 0.f, bhn = 0.f;
    if (active) { bhr = b_hh[j]; bhz = b_hh[H_DIM+j]; bhn = b_hh[2*H_DIM+j]; }
    __syncthreads();

    const uint4* w4 = sw4 + (size_t)u*768;   // [gate][chunk][lane] = [3][8][32]

    for (int t = 0; t < T_STEPS; t++) {
        // Prefetch per-unit scalars (xi in DRAM; latency hidden under GEMV).
        float xr = 0.f, xz = 0.f, xn = 0.f, hprev = 0.f;
        if (active && lane == 0) {
            const float* xirow = g_xi + (size_t)t*G3H;
            xr = xirow[j]; xz = xirow[H_DIM+j]; xn = xirow[2*H_DIM+j];
            hprev = smem_h[j];
        }

        // GEMV: 3 gate rows x 2048, fp16 weights from SMEM, fp32 h from SMEM.
        unsigned long long a0 = 0ull, a1 = 0ull, a2 = 0ull;
        #pragma unroll
        for (int c = 0; c < 8; c++) {
            float4 ha = *(const float4*)&smem_h[c*256 + lane*4];        // conflict-free
            float4 hb = *(const float4*)&smem_h[c*256 + 128 + lane*4];  // conflict-free
            unsigned long long h01 = pk2(ha.x, ha.y), h23 = pk2(ha.z, ha.w);
            unsigned long long h45 = pk2(hb.x, hb.y), h67 = pk2(hb.z, hb.w);
            fma8(a0, w4[0*256 + c*32 + lane], h01, h23, h45, h67);
            fma8(a1, w4[1*256 + c*32 + lane], h01, h23, h45, h67);
            fma8(a2, w4[2*256 + c*32 + lane], h01, h23, h45, h67);
        }
        float s0 = unpack_sum(a0), s1 = unpack_sum(a1), s2 = unpack_sum(a2);
        #pragma unroll
        for (int off = 16; off > 0; off >>= 1) {
            s0 += __shfl_xor_sync(0xffffffffu, s0, off);
            s1 += __shfl_xor_sync(0xffffffffu, s1, off);
            s2 += __shfl_xor_sync(0xffffffffu, s2, off);
        }
        if (active && lane == 0) {
            float r = sigmoid_f(xr + s0 + bhr);
            float z = sigmoid_f(xz + s1 + bhz);
            float n = tanh_f(xn + r*(s2 + bhn));
            g_hs[(size_t)t*H_DIM + j] = (1.0f - z)*n + z*hprev;
        }

        // ---- grid barrier (release/acquire; all 147 CTAs co-resident) ----
        __threadfence();          // make lane0 h-stores gpu-visible (cheap insurance)
        __syncthreads();
        if (tid == 0) {
            unsigned gen;
            asm volatile("ld.relaxed.gpu.global.u32 %0, [%1];" : "=r"(gen) : "l"(&g_bar_gen));
            unsigned old;
            asm volatile("atom.acq_rel.gpu.global.add.u32 %0, [%1], 1;"
                         : "=r"(old) : "l"(&g_bar_cnt) : "memory");
            if (old == SCAN_NB - 1u) {
                asm volatile("st.relaxed.gpu.global.u32 [%0], %1;"
                             :: "l"(&g_bar_cnt), "r"(0u) : "memory");
                asm volatile("st.release.gpu.global.u32 [%0], %1;"
                             :: "l"(&g_bar_gen), "r"(gen + 1u) : "memory");
            } else {
                unsigned cur;
                do {
                    asm volatile("ld.acquire.gpu.global.u32 %0, [%1];"
                                 : "=r"(cur) : "l"(&g_bar_gen) : "memory");
                } while (cur == gen);
            }
        }
        __syncthreads();

        // Cooperative coalesced stage of h_t into SMEM (512 float4 / 448 threads).
        const float4* hsrc = reinterpret_cast<const float4*>(g_hs + (size_t)t*H_DIM);
        float4* hdst = reinterpret_cast<float4*>(smem_h);
        for (int i = tid; i < H_DIM/4; i += SCAN_THREADS) hdst[i] = hsrc[i];
        __syncthreads();
    }
}

// ---------------- launch ----------------------------------------------------
extern "C" void kernel_launch(void* const* d_in, const int* in_sizes, int n_in,
                              void* d_out, int out_size)
{
    const float* obs  = (const float*)d_in[0];
    const float* W_ih = (const float*)d_in[1];
    const float* W_hh = (const float*)d_in[2];
    const float* b_ih = (const float*)d_in[3];
    const float* b_hh = (const float*)d_in[4];
    const float* W_o  = (const float*)d_in[5];
    const float* b_o  = (const float*)d_in[6];
    const float* W_d  = (const float*)d_in[7];
    const float* b_d  = (const float*)d_in[8];
    float* out = (float*)d_out;

    float* xi = nullptr; float* hs = nullptr;
    cudaGetSymbolAddress((void**)&xi, g_xi);
    cudaGetSymbolAddress((void**)&hs, g_hs);

    // 1) W_hh -> fp16 permuted layout
    {
        int total = H_DIM * 3 * 8 * 32;
        convert_whh_kernel<<<(total + 255)/256, 256>>>(W_hh);
    }

    // 2) xi = obs @ W_ih^T + b_ih   [8192 x 6144], K=1024
    gemm_abt_kernel<<<dim3(G3H/128, T_STEPS/128), 256>>>(
        obs, W_ih, b_ih, xi, T_STEPS, G3H, O_DIM);

    // 3) sequential GRU scan (persistent kernel, 8192 internal steps)
    cudaFuncSetAttribute(gru_scan_kernel,
                         cudaFuncAttributeMaxDynamicSharedMemorySize, SCAN_SMEM);
    gru_scan_kernel<<<SCAN_NB, SCAN_THREADS, SCAN_SMEM>>>(b_hh);

    // 4) o_logits = hs @ W_o^T + b_o ; d_logits = hs @ W_d^T + b_d
    gemm_abt_kernel<<<dim3(A_DIM/128, T_STEPS/128), 256>>>(
        hs, W_o, b_o, out, T_STEPS, A_DIM, H_DIM);
    gemm_abt_kernel<<<dim3(A_DIM/128, T_STEPS/128), 256>>>(
        hs, W_d, b_d, out + (size_t)T_STEPS * A_DIM, T_STEPS, A_DIM, H_DIM);
}

// round 5
// speedup vs baseline: 1.5466x; 1.4954x over previous
#include <cuda_runtime.h>
#include <cuda_fp16.h>
#include <cstdint>

#define T_STEPS 8192
#define O_DIM   1024
#define H_DIM   2048
#define A_DIM   512
#define G3H     (3*H_DIM)

// Scan persistent-kernel config: 147 blocks x 14 hidden units, 1 warp per unit.
#define SCAN_NB      147
#define SCAN_UPB     14
#define SCAN_THREADS (SCAN_UPB*32)
// SMEM: n-gate fp16 weights (14*2048*2 = 57344 B) + h staging as half2 (4096 B)
#define SCAN_W_BYTES (SCAN_UPB*H_DIM*2)
#define SCAN_SMEM    (SCAN_W_BYTES + H_DIM*2)

// ---------------- scratch (device globals: allocation-free rule) ------------
__device__ float  g_xi[(size_t)T_STEPS * G3H];    // 192 MB: precomputed input projections
__device__ float  g_hs[(size_t)T_STEPS * H_DIM];  // 64 MB: hidden states (fp32, for GEMMs)
__device__ uint4  g_whh4[(size_t)H_DIM * 3 * 8 * 32]; // 24 MB fp16 W_hh, packed half2 layout
__device__ __align__(16) __half g_hh[2 * H_DIM];  // double-buffered fp16 h (cross-CTA)
__device__ unsigned g_bar_cnt;
__device__ unsigned g_bar_gen;

// ---------------- W_hh fp32 -> fp16 packed relayout --------------------------
// For unit j, gate g, chunk c (0..7), lane l (0..31):
//   g_whh4[((j*3+g)*8 + c)*32 + l] = half2x4 of W_hh[g*H+j][k], k = c*256 + l*8 + {0..7}
// In the scan, lane l's 8 h values are one contiguous uint4 (4 half2) in SMEM: index c*32+l.
__global__ void convert_whh_kernel(const float* __restrict__ W) {
    int idx = blockIdx.x * blockDim.x + threadIdx.x;      // 0 .. 6144*256-1
    if (idx >= H_DIM * 3 * 8 * 32) return;
    int l  = idx & 31;
    int c  = (idx >> 5) & 7;
    int gj = idx >> 8;            // j*3 + g
    int g  = gj % 3;
    int j  = gj / 3;
    const float* src = W + (size_t)(g*H_DIM + j)*H_DIM + c*256 + l*8;
    float4 v0 = *(const float4*)src;
    float4 v1 = *(const float4*)(src + 4);
    __half2 q0 = __floats2half2_rn(v0.x, v0.y);
    __half2 q1 = __floats2half2_rn(v0.z, v0.w);
    __half2 q2 = __floats2half2_rn(v1.x, v1.y);
    __half2 q3 = __floats2half2_rn(v1.z, v1.w);
    uint4 o;
    o.x = *reinterpret_cast<unsigned*>(&q0);
    o.y = *reinterpret_cast<unsigned*>(&q1);
    o.z = *reinterpret_cast<unsigned*>(&q2);
    o.w = *reinterpret_cast<unsigned*>(&q3);
    g_whh4[idx] = o;
}

// ---------------- generic C = A * B^T + bias (fp32 SIMT, 128x128x16) --------
__global__ __launch_bounds__(256) void gemm_abt_kernel(
    const float* __restrict__ A, const float* __restrict__ B,
    const float* __restrict__ bias, float* __restrict__ C,
    int M, int N, int K)
{
    __shared__ __align__(16) float As[16][132];
    __shared__ __align__(16) float Bs[16][132];
    const int tid = threadIdx.x;
    const int tx = tid & 15, ty = tid >> 4;
    const int m0 = blockIdx.y * 128, n0 = blockIdx.x * 128;

    float acc[8][8];
    #pragma unroll
    for (int i = 0; i < 8; i++)
        #pragma unroll
        for (int j = 0; j < 8; j++) acc[i][j] = 0.0f;

    for (int kt = 0; kt < K; kt += 16) {
        #pragma unroll
        for (int s = 0; s < 2; s++) {
            int f = tid + s*256;
            int row = f >> 2;
            int kq = (f & 3) << 2;
            float4 va = *(const float4*)(A + (size_t)(m0+row)*K + kt + kq);
            As[kq+0][row] = va.x; As[kq+1][row] = va.y;
            As[kq+2][row] = va.z; As[kq+3][row] = va.w;
            float4 vb = *(const float4*)(B + (size_t)(n0+row)*K + kt + kq);
            Bs[kq+0][row] = vb.x; Bs[kq+1][row] = vb.y;
            Bs[kq+2][row] = vb.z; Bs[kq+3][row] = vb.w;
        }
        __syncthreads();
        #pragma unroll
        for (int k = 0; k < 16; k++) {
            float a[8], bb[8];
            *(float4*)(a)    = *(const float4*)&As[k][ty*8];
            *(float4*)(a+4)  = *(const float4*)&As[k][ty*8+4];
            *(float4*)(bb)   = *(const float4*)&Bs[k][tx*8];
            *(float4*)(bb+4) = *(const float4*)&Bs[k][tx*8+4];
            #pragma unroll
            for (int i = 0; i < 8; i++)
                #pragma unroll
                for (int j = 0; j < 8; j++)
                    acc[i][j] = fmaf(a[i], bb[j], acc[i][j]);
        }
        __syncthreads();
    }

    float4 bv0 = *(const float4*)&bias[n0 + tx*8];
    float4 bv1 = *(const float4*)&bias[n0 + tx*8 + 4];
    #pragma unroll
    for (int i = 0; i < 8; i++) {
        float4 o0, o1;
        o0.x = acc[i][0]+bv0.x; o0.y = acc[i][1]+bv0.y;
        o0.z = acc[i][2]+bv0.z; o0.w = acc[i][3]+bv0.w;
        o1.x = acc[i][4]+bv1.x; o1.y = acc[i][5]+bv1.y;
        o1.z = acc[i][6]+bv1.z; o1.w = acc[i][7]+bv1.w;
        float* crow = C + (size_t)(m0 + ty*8 + i)*N + n0 + tx*8;
        *(float4*)(crow)   = o0;
        *(float4*)(crow+4) = o1;
    }
}

// ---------------- scan helpers ----------------------------------------------
__device__ __forceinline__ float sigmoid_f(float x) {
    return 1.0f / (1.0f + __expf(-x));
}
__device__ __forceinline__ float tanh_f(float x) {
    float e = __expf(-2.0f * fabsf(x));
    float t = (1.0f - e) / (1.0f + e);
    return copysignf(t, x);
}
__device__ __forceinline__ __half2 u2h(unsigned u) {
    return *reinterpret_cast<__half2*>(&u);
}
// acc[0..3] += w (4 half2) * h (4 half2), elementwise fp16x2
__device__ __forceinline__ void hfma_u4(__half2 acc[4], uint4 w, uint4 h) {
    acc[0] = __hfma2(u2h(w.x), u2h(h.x), acc[0]);
    acc[1] = __hfma2(u2h(w.y), u2h(h.y), acc[1]);
    acc[2] = __hfma2(u2h(w.z), u2h(h.z), acc[2]);
    acc[3] = __hfma2(u2h(w.w), u2h(h.w), acc[3]);
}
__device__ __forceinline__ float acc_to_f32(const __half2 acc[4]) {
    __half2 a = __hadd2(acc[0], acc[1]);
    __half2 b = __hadd2(acc[2], acc[3]);
    float2 fa = __half22float2(a);
    float2 fb = __half22float2(b);
    return (fa.x + fa.y) + (fb.x + fb.y);
}

// ---------------- GRU scan (persistent; r,z weights in regs, n in SMEM) -----
__global__ __launch_bounds__(SCAN_THREADS, 1) void gru_scan_kernel(const float* __restrict__ b_hh)
{
    extern __shared__ __align__(16) char smem_raw[];
    uint4* sn4 = reinterpret_cast<uint4*>(smem_raw);                  // n-gate weights [14][8][32] uint4
    uint4* sh4 = reinterpret_cast<uint4*>(smem_raw + SCAN_W_BYTES);   // h as half2: 256 uint4

    const int tid  = threadIdx.x;
    const int u    = tid >> 5;
    const int lane = tid & 31;
    const int j    = blockIdx.x * SCAN_UPB + u;
    const bool active = (j < H_DIM);

    // Zero all SMEM (h region for t=0; weight region for inactive tail warps).
    for (int i = tid; i < SCAN_SMEM/16; i += SCAN_THREADS)
        reinterpret_cast<uint4*>(smem_raw)[i] = make_uint4(0,0,0,0);
    __syncthreads();

    // r,z gate weights -> registers (64 regs/lane); n gate -> SMEM.
    uint4 wr[8], wz[8];
    #pragma unroll
    for (int c = 0; c < 8; c++) { wr[c] = make_uint4(0,0,0,0); wz[c] = make_uint4(0,0,0,0); }
    if (active) {
        #pragma unroll
        for (int c = 0; c < 8; c++) {
            wr[c] = g_whh4[((size_t)(j*3 + 0)*8 + c)*32 + lane];
            wz[c] = g_whh4[((size_t)(j*3 + 1)*8 + c)*32 + lane];
            sn4[(u*8 + c)*32 + lane] = g_whh4[((size_t)(j*3 + 2)*8 + c)*32 + lane];
        }
    }
    float bhr = 0.f, bhz = 0.f, bhn = 0.f;
    if (active) { bhr = b_hh[j]; bhz = b_hh[H_DIM+j]; bhn = b_hh[2*H_DIM+j]; }
    __syncthreads();

    const uint4* wn = sn4 + u*256;

    // Prefetch xi for t=0 (lane 0 of each active warp).
    float pxr = 0.f, pxz = 0.f, pxn = 0.f;
    if (active && lane == 0) {
        pxr = g_xi[j]; pxz = g_xi[H_DIM + j]; pxn = g_xi[2*H_DIM + j];
    }
    float hprev = 0.f;

    for (int t = 0; t < T_STEPS; t++) {
        const float xr = pxr, xz = pxz, xn = pxn;
        // Prefetch next step's xi (hidden under this step's GEMV + barrier).
        if (active && lane == 0) {
            int tn = (t + 1 < T_STEPS) ? (t + 1) : t;
            const float* xirow = g_xi + (size_t)tn * G3H;
            pxr = xirow[j]; pxz = xirow[H_DIM+j]; pxn = xirow[2*H_DIM+j];
        }

        // GEMV: 3 gates x 2048, all fp16x2 (h fp16 in SMEM). 96 HFMA2 / warp.
        __half2 ar[4], az[4], an[4];
        #pragma unroll
        for (int i = 0; i < 4; i++) {
            ar[i] = __half2half2(__ushort_as_half(0));
            az[i] = ar[i]; an[i] = ar[i];
        }
        #pragma unroll
        for (int c = 0; c < 8; c++) {
            uint4 hq = sh4[c*32 + lane];
            hfma_u4(ar, wr[c], hq);
            hfma_u4(az, wz[c], hq);
            hfma_u4(an, wn[c*32 + lane], hq);
        }
        float s0 = acc_to_f32(ar), s1 = acc_to_f32(az), s2 = acc_to_f32(an);
        #pragma unroll
        for (int off = 16; off > 0; off >>= 1) {
            s0 += __shfl_xor_sync(0xffffffffu, s0, off);
            s1 += __shfl_xor_sync(0xffffffffu, s1, off);
            s2 += __shfl_xor_sync(0xffffffffu, s2, off);
        }

        if (active && lane == 0) {
            float r = sigmoid_f(xr + s0 + bhr);
            float z = sigmoid_f(xz + s1 + bhz);
            float n = tanh_f(xn + r*(s2 + bhn));
            float hnew = (1.0f - z)*n + z*hprev;
            hprev = hnew;
            g_hs[(size_t)t*H_DIM + j] = hnew;                 // fp32 (output GEMMs)
            g_hh[(t & 1)*H_DIM + j] = __float2half_rn(hnew);  // fp16 (cross-CTA broadcast)
        }

        // ---- grid barrier (release/acquire; all 147 CTAs co-resident) ----
        __syncthreads();
        if (tid == 0) {
            unsigned gen;
            asm volatile("ld.relaxed.gpu.global.u32 %0, [%1];" : "=r"(gen) : "l"(&g_bar_gen));
            unsigned old;
            asm volatile("atom.acq_rel.gpu.global.add.u32 %0, [%1], 1;"
                         : "=r"(old) : "l"(&g_bar_cnt) : "memory");
            if (old == SCAN_NB - 1u) {
                asm volatile("st.relaxed.gpu.global.u32 [%0], %1;"
                             :: "l"(&g_bar_cnt), "r"(0u) : "memory");
                asm volatile("st.release.gpu.global.u32 [%0], %1;"
                             :: "l"(&g_bar_gen), "r"(gen + 1u) : "memory");
            } else {
                unsigned cur;
                do {
                    asm volatile("ld.acquire.gpu.global.u32 %0, [%1];"
                                 : "=r"(cur) : "l"(&g_bar_gen) : "memory");
                } while (cur == gen);
            }
        }
        __syncthreads();

        // Stage h_t (fp16, 4 KB) into SMEM: 256 uint4, one per thread for tid<256.
        if (tid < 256)
            sh4[tid] = reinterpret_cast<const uint4*>(g_hh)[(t & 1)*256 + tid];
        __syncthreads();
    }
}

// ---------------- launch ----------------------------------------------------
extern "C" void kernel_launch(void* const* d_in, const int* in_sizes, int n_in,
                              void* d_out, int out_size)
{
    const float* obs  = (const float*)d_in[0];
    const float* W_ih = (const float*)d_in[1];
    const float* W_hh = (const float*)d_in[2];
    const float* b_ih = (const float*)d_in[3];
    const float* b_hh = (const float*)d_in[4];
    const float* W_o  = (const float*)d_in[5];
    const float* b_o  = (const float*)d_in[6];
    const float* W_d  = (const float*)d_in[7];
    const float* b_d  = (const float*)d_in[8];
    float* out = (float*)d_out;

    float* xi = nullptr; float* hs = nullptr;
    cudaGetSymbolAddress((void**)&xi, g_xi);
    cudaGetSymbolAddress((void**)&hs, g_hs);

    // 1) W_hh -> fp16 packed layout
    {
        int total = H_DIM * 3 * 8 * 32;
        convert_whh_kernel<<<(total + 255)/256, 256>>>(W_hh);
    }

    // 2) xi = obs @ W_ih^T + b_ih   [8192 x 6144], K=1024
    gemm_abt_kernel<<<dim3(G3H/128, T_STEPS/128), 256>>>(
        obs, W_ih, b_ih, xi, T_STEPS, G3H, O_DIM);

    // 3) sequential GRU scan (persistent kernel, 8192 internal steps)
    cudaFuncSetAttribute(gru_scan_kernel,
                         cudaFuncAttributeMaxDynamicSharedMemorySize, SCAN_SMEM);
    gru_scan_kernel<<<SCAN_NB, SCAN_THREADS, SCAN_SMEM>>>(b_hh);

    // 4) o_logits = hs @ W_o^T + b_o ; d_logits = hs @ W_d^T + b_d
    gemm_abt_kernel<<<dim3(A_DIM/128, T_STEPS/128), 256>>>(
        hs, W_o, b_o, out, T_STEPS, A_DIM, H_DIM);
    gemm_abt_kernel<<<dim3(A_DIM/128, T_STEPS/128), 256>>>(
        hs, W_d, b_d, out + (size_t)T_STEPS * A_DIM, T_STEPS, A_DIM, H_DIM);
}

// round 6
// speedup vs baseline: 1.6595x; 1.0730x over previous
#include <cuda_runtime.h>
#include <cuda_fp16.h>
#include <cstdint>

#define T_STEPS 8192
#define O_DIM   1024
#define H_DIM   2048
#define A_DIM   512
#define G3H     (3*H_DIM)

// Scan persistent-kernel config: 147 blocks x 14 hidden units, 1 warp per unit.
#define SCAN_NB      147
#define SCAN_UPB     14
#define SCAN_THREADS (SCAN_UPB*32)

// ---------------- scratch (device globals: allocation-free rule) ------------
__device__ float  g_xi[(size_t)T_STEPS * G3H];        // 192 MB: input projections
__device__ float  g_hs[(size_t)T_STEPS * H_DIM];      // 64 MB: hidden states (fp32, GEMMs)
__device__ uint4  g_whh4[(size_t)H_DIM * 3 * 8 * 32]; // 24 MB fp16 W_hh, packed half2 layout
__device__ __align__(16) __half g_hh[2 * H_DIM];      // double-buffered fp16 h (cross-CTA)
__device__ unsigned g_bar_cnt;                         // monotonic barrier counter

__global__ void reset_barrier_kernel() { g_bar_cnt = 0u; }

// ---------------- W_hh fp32 -> fp16 packed relayout --------------------------
// g_whh4[((j*3+g)*8 + c)*32 + l] = half2x4 of W_hh[g*H+j][k], k = c*256 + l*8 + {0..7}
__global__ void convert_whh_kernel(const float* __restrict__ W) {
    int idx = blockIdx.x * blockDim.x + threadIdx.x;      // 0 .. 6144*256-1
    if (idx >= H_DIM * 3 * 8 * 32) return;
    int l  = idx & 31;
    int c  = (idx >> 5) & 7;
    int gj = idx >> 8;            // j*3 + g
    int g  = gj % 3;
    int j  = gj / 3;
    const float* src = W + (size_t)(g*H_DIM + j)*H_DIM + c*256 + l*8;
    float4 v0 = *(const float4*)src;
    float4 v1 = *(const float4*)(src + 4);
    __half2 q0 = __floats2half2_rn(v0.x, v0.y);
    __half2 q1 = __floats2half2_rn(v0.z, v0.w);
    __half2 q2 = __floats2half2_rn(v1.x, v1.y);
    __half2 q3 = __floats2half2_rn(v1.z, v1.w);
    uint4 o;
    o.x = *reinterpret_cast<unsigned*>(&q0);
    o.y = *reinterpret_cast<unsigned*>(&q1);
    o.z = *reinterpret_cast<unsigned*>(&q2);
    o.w = *reinterpret_cast<unsigned*>(&q3);
    g_whh4[idx] = o;
}

// ---------------- generic C = A * B^T + bias (fp32 SIMT, 128x128x16) --------
__global__ __launch_bounds__(256) void gemm_abt_kernel(
    const float* __restrict__ A, const float* __restrict__ B,
    const float* __restrict__ bias, float* __restrict__ C,
    int M, int N, int K)
{
    __shared__ __align__(16) float As[16][132];
    __shared__ __align__(16) float Bs[16][132];
    const int tid = threadIdx.x;
    const int tx = tid & 15, ty = tid >> 4;
    const int m0 = blockIdx.y * 128, n0 = blockIdx.x * 128;

    float acc[8][8];
    #pragma unroll
    for (int i = 0; i < 8; i++)
        #pragma unroll
        for (int j = 0; j < 8; j++) acc[i][j] = 0.0f;

    for (int kt = 0; kt < K; kt += 16) {
        #pragma unroll
        for (int s = 0; s < 2; s++) {
            int f = tid + s*256;
            int row = f >> 2;
            int kq = (f & 3) << 2;
            float4 va = *(const float4*)(A + (size_t)(m0+row)*K + kt + kq);
            As[kq+0][row] = va.x; As[kq+1][row] = va.y;
            As[kq+2][row] = va.z; As[kq+3][row] = va.w;
            float4 vb = *(const float4*)(B + (size_t)(n0+row)*K + kt + kq);
            Bs[kq+0][row] = vb.x; Bs[kq+1][row] = vb.y;
            Bs[kq+2][row] = vb.z; Bs[kq+3][row] = vb.w;
        }
        __syncthreads();
        #pragma unroll
        for (int k = 0; k < 16; k++) {
            float a[8], bb[8];
            *(float4*)(a)    = *(const float4*)&As[k][ty*8];
            *(float4*)(a+4)  = *(const float4*)&As[k][ty*8+4];
            *(float4*)(bb)   = *(const float4*)&Bs[k][tx*8];
            *(float4*)(bb+4) = *(const float4*)&Bs[k][tx*8+4];
            #pragma unroll
            for (int i = 0; i < 8; i++)
                #pragma unroll
                for (int j = 0; j < 8; j++)
                    acc[i][j] = fmaf(a[i], bb[j], acc[i][j]);
        }
        __syncthreads();
    }

    float4 bv0 = *(const float4*)&bias[n0 + tx*8];
    float4 bv1 = *(const float4*)&bias[n0 + tx*8 + 4];
    #pragma unroll
    for (int i = 0; i < 8; i++) {
        float4 o0, o1;
        o0.x = acc[i][0]+bv0.x; o0.y = acc[i][1]+bv0.y;
        o0.z = acc[i][2]+bv0.z; o0.w = acc[i][3]+bv0.w;
        o1.x = acc[i][4]+bv1.x; o1.y = acc[i][5]+bv1.y;
        o1.z = acc[i][6]+bv1.z; o1.w = acc[i][7]+bv1.w;
        float* crow = C + (size_t)(m0 + ty*8 + i)*N + n0 + tx*8;
        *(float4*)(crow)   = o0;
        *(float4*)(crow+4) = o1;
    }
}

// ---------------- scan helpers ----------------------------------------------
__device__ __forceinline__ float sigmoid_f(float x) {
    return 1.0f / (1.0f + __expf(-x));
}
__device__ __forceinline__ float tanh_f(float x) {
    float e = __expf(-2.0f * fabsf(x));
    float t = (1.0f - e) / (1.0f + e);
    return copysignf(t, x);
}
__device__ __forceinline__ __half2 u2h(unsigned u) {
    return *reinterpret_cast<__half2*>(&u);
}
__device__ __forceinline__ void hfma_u4(__half2 acc[4], uint4 w, uint4 h) {
    acc[0] = __hfma2(u2h(w.x), u2h(h.x), acc[0]);
    acc[1] = __hfma2(u2h(w.y), u2h(h.y), acc[1]);
    acc[2] = __hfma2(u2h(w.z), u2h(h.z), acc[2]);
    acc[3] = __hfma2(u2h(w.w), u2h(h.w), acc[3]);
}
__device__ __forceinline__ float acc_to_f32(const __half2 acc[4]) {
    __half2 a = __hadd2(acc[0], acc[1]);
    __half2 b = __hadd2(acc[2], acc[3]);
    float2 fa = __half22float2(a);
    float2 fb = __half22float2(b);
    return (fa.x + fa.y) + (fb.x + fb.y);
}

// ---------------- GRU scan (persistent; ALL gate weights in registers) ------
__global__ __launch_bounds__(SCAN_THREADS, 1) void gru_scan_kernel(const float* __restrict__ b_hh)
{
    __shared__ __align__(16) uint4 sh4[H_DIM/8];   // h as half2: 256 uint4 = 4 KB

    const int tid  = threadIdx.x;
    const int u    = tid >> 5;
    const int lane = tid & 31;
    const int j    = blockIdx.x * SCAN_UPB + u;
    const bool active = (j < H_DIM);

    // Zero h buffer (t=0 uses h = 0).
    for (int i = tid; i < H_DIM/8; i += SCAN_THREADS) sh4[i] = make_uint4(0,0,0,0);

    // All three gate weight rows -> registers (96 regs/lane).
    uint4 wr[8], wz[8], wn[8];
    #pragma unroll
    for (int c = 0; c < 8; c++) {
        wr[c] = make_uint4(0,0,0,0); wz[c] = wr[c]; wn[c] = wr[c];
    }
    if (active) {
        #pragma unroll
        for (int c = 0; c < 8; c++) {
            wr[c] = g_whh4[((size_t)(j*3 + 0)*8 + c)*32 + lane];
            wz[c] = g_whh4[((size_t)(j*3 + 1)*8 + c)*32 + lane];
            wn[c] = g_whh4[((size_t)(j*3 + 2)*8 + c)*32 + lane];
        }
    }
    float bhr = 0.f, bhz = 0.f, bhn = 0.f;
    if (active) { bhr = b_hh[j]; bhz = b_hh[H_DIM+j]; bhn = b_hh[2*H_DIM+j]; }
    __syncthreads();

    // Prefetch xi for t=0.
    float pxr = 0.f, pxz = 0.f, pxn = 0.f;
    if (active && lane == 0) {
        pxr = g_xi[j]; pxz = g_xi[H_DIM + j]; pxn = g_xi[2*H_DIM + j];
    }
    float hprev = 0.f;

    for (int t = 0; t < T_STEPS; t++) {
        const float xr = pxr, xz = pxz, xn = pxn;
        // Prefetch next step's xi (hidden under this step's GEMV + barrier).
        if (active && lane == 0) {
            int tn = (t + 1 < T_STEPS) ? (t + 1) : t;
            const float* xirow = g_xi + (size_t)tn * G3H;
            pxr = xirow[j]; pxz = xirow[H_DIM+j]; pxn = xirow[2*H_DIM+j];
        }

        // GEMV: 3 gates x 2048, fp16x2. 96 HFMA2 + 8 LDS.128 per lane.
        __half2 ar[4], az[4], an[4];
        #pragma unroll
        for (int i = 0; i < 4; i++) {
            ar[i] = __half2half2(__ushort_as_half(0));
            az[i] = ar[i]; an[i] = ar[i];
        }
        #pragma unroll
        for (int c = 0; c < 8; c++) {
            uint4 hq = sh4[c*32 + lane];
            hfma_u4(ar, wr[c], hq);
            hfma_u4(az, wz[c], hq);
            hfma_u4(an, wn[c], hq);
        }
        float s0 = acc_to_f32(ar), s1 = acc_to_f32(az), s2 = acc_to_f32(an);
        #pragma unroll
        for (int off = 16; off > 0; off >>= 1) {
            s0 += __shfl_xor_sync(0xffffffffu, s0, off);
            s1 += __shfl_xor_sync(0xffffffffu, s1, off);
            s2 += __shfl_xor_sync(0xffffffffu, s2, off);
        }

        if (active && lane == 0) {
            float r = sigmoid_f(xr + s0 + bhr);
            float z = sigmoid_f(xz + s1 + bhz);
            float n = tanh_f(xn + r*(s2 + bhn));
            float hnew = (1.0f - z)*n + z*hprev;
            hprev = hnew;
            g_hs[(size_t)t*H_DIM + j] = hnew;                 // fp32 (output GEMMs)
            g_hh[(t & 1)*H_DIM + j] = __float2half_rn(hnew);  // fp16 (cross-CTA broadcast)
        }

        if (t == T_STEPS - 1) break;   // no successor needs h via the barrier

        // ---- barrier + h staging, fused into warp 0 ----
        __syncthreads();   // all CTA h stores program-ordered before tid0's release
        if (u == 0) {
            if (lane == 0)
                asm volatile("red.release.gpu.global.add.u32 [%0], %1;"
                             :: "l"(&g_bar_cnt), "r"(1u) : "memory");
            const unsigned target = (unsigned)(t + 1) * (unsigned)SCAN_NB;
            unsigned cur;
            do {  // acquire load: orders + refreshes L1 for the g_hh read below
                asm volatile("ld.acquire.gpu.global.u32 %0, [%1];"
                             : "=r"(cur) : "l"(&g_bar_cnt) : "memory");
            } while (cur < target);
            // Stage h_t (4 KB): 8 LDG.128 per lane, MLP=8, then STS.
            const uint4* src = reinterpret_cast<const uint4*>(g_hh) + (t & 1)*256;
            uint4 v[8];
            #pragma unroll
            for (int i = 0; i < 8; i++) v[i] = src[lane + i*32];
            #pragma unroll
            for (int i = 0; i < 8; i++) sh4[lane + i*32] = v[i];
        }
        __syncthreads();
    }
}

// ---------------- launch ----------------------------------------------------
extern "C" void kernel_launch(void* const* d_in, const int* in_sizes, int n_in,
                              void* d_out, int out_size)
{
    const float* obs  = (const float*)d_in[0];
    const float* W_ih = (const float*)d_in[1];
    const float* W_hh = (const float*)d_in[2];
    const float* b_ih = (const float*)d_in[3];
    const float* b_hh = (const float*)d_in[4];
    const float* W_o  = (const float*)d_in[5];
    const float* b_o  = (const float*)d_in[6];
    const float* W_d  = (const float*)d_in[7];
    const float* b_d  = (const float*)d_in[8];
    float* out = (float*)d_out;

    float* xi = nullptr; float* hs = nullptr;
    cudaGetSymbolAddress((void**)&xi, g_xi);
    cudaGetSymbolAddress((void**)&hs, g_hs);

    // 0) reset monotonic barrier counter (graph replays reuse device globals)
    reset_barrier_kernel<<<1, 1>>>();

    // 1) W_hh -> fp16 packed layout
    {
        int total = H_DIM * 3 * 8 * 32;
        convert_whh_kernel<<<(total + 255)/256, 256>>>(W_hh);
    }

    // 2) xi = obs @ W_ih^T + b_ih   [8192 x 6144], K=1024
    gemm_abt_kernel<<<dim3(G3H/128, T_STEPS/128), 256>>>(
        obs, W_ih, b_ih, xi, T_STEPS, G3H, O_DIM);

    // 3) sequential GRU scan (persistent kernel, 8192 internal steps)
    gru_scan_kernel<<<SCAN_NB, SCAN_THREADS>>>(b_hh);

    // 4) o_logits = hs @ W_o^T + b_o ; d_logits = hs @ W_d^T + b_d
    gemm_abt_kernel<<<dim3(A_DIM/128, T_STEPS/128), 256>>>(
        hs, W_o, b_o, out, T_STEPS, A_DIM, H_DIM);
    gemm_abt_kernel<<<dim3(A_DIM/128, T_STEPS/128), 256>>>(
        hs, W_d, b_d, out + (size_t)T_STEPS * A_DIM, T_STEPS, A_DIM, H_DIM);
}